// round 7
// baseline (speedup 1.0000x reference)
#include <cuda_runtime.h>
#include <cstdint>
#include <cstddef>

#define TT 512
#define BB 16
#define EE 1024
#define HH 512
#define G3 1536
#define SENT 0x7FC00001u

// pre-gate scratch [d][t][col][b]
__device__ float g_preg[(size_t)2 * TT * G3 * BB];
// tf32-pre-rounded h staging [d][t][k][b]; sentinel-filled each launch
__device__ float g_hstage[(size_t)2 * TT * HH * BB];

static __device__ __forceinline__ uint32_t f2tf(float f) {
    uint32_t r; asm("cvt.rna.tf32.f32 %0, %1;" : "=r"(r) : "f"(f)); return r;
}
static __device__ __forceinline__ float f2tff(float f) { return __uint_as_float(f2tf(f)); }
static __device__ __forceinline__ float rcpa(float x) {
    float r; asm("rcp.approx.f32 %0, %1;" : "=f"(r) : "f"(x)); return r;
}

static __device__ __forceinline__ void mma8(float& d0, float& d1, float& d2, float& d3,
                                            uint32_t a0, uint32_t a1, uint32_t a2, uint32_t a3,
                                            uint32_t b0, uint32_t b1) {
    asm volatile(
        "mma.sync.aligned.m16n8k8.row.col.f32.tf32.tf32.f32 "
        "{%0,%1,%2,%3}, {%4,%5,%6,%7}, {%8,%9}, {%0,%1,%2,%3};"
        : "+f"(d0), "+f"(d1), "+f"(d2), "+f"(d3)
        : "r"(a0), "r"(a1), "r"(a2), "r"(a3), "r"(b0), "r"(b1));
}

// L1-bypassing (gpu-scope) loads/stores for the producer-consumer handoff
static __device__ __forceinline__ float4 ld_rlx4(const float* p) {
    float4 v;
    asm volatile("ld.relaxed.gpu.global.v4.f32 {%0,%1,%2,%3}, [%4];"
                 : "=f"(v.x), "=f"(v.y), "=f"(v.z), "=f"(v.w) : "l"(p) : "memory");
    return v;
}
static __device__ __forceinline__ void st_rlx4(float* p, float4 v) {
    asm volatile("st.relaxed.gpu.global.v4.f32 [%0], {%1,%2,%3,%4};"
                 :: "l"(p), "f"(v.x), "f"(v.y), "f"(v.z), "f"(v.w) : "memory");
}
static __device__ __forceinline__ bool has_sent(float4 v) {
    return (__float_as_uint(v.x) == SENT) | (__float_as_uint(v.y) == SENT) |
           (__float_as_uint(v.z) == SENT) | (__float_as_uint(v.w) == SENT);
}

// fill g_hstage with the sentinel pattern (runs first, every launch)
__global__ void fill_sentinel_kernel() {
    const size_t n4 = (size_t)2 * TT * HH * BB / 4;
    uint4 s = make_uint4(SENT, SENT, SENT, SENT);
    uint4* p = reinterpret_cast<uint4*>(g_hstage);
    for (size_t i = blockIdx.x * (size_t)blockDim.x + threadIdx.x; i < n4;
         i += (size_t)gridDim.x * blockDim.x)
        p[i] = s;
}

// ---------------------------------------------------------------------------
// Phase 1: pre-gates = x @ W_x^T + bias, both directions (tf32 mma GEMM).
// M = 8192, N = 1536, K = 1024. CTA tile 128x128x32, 8 warps, warp 64x32.
// 2-stage double-buffered SMEM pipeline (LDG k+1 overlaps mma on k).
// ---------------------------------------------------------------------------
#define PTILE (128 * 36)

__global__ __launch_bounds__(256) void pregemm_kernel(
    const float* __restrict__ x,
    const float* __restrict__ wf, const float* __restrict__ bf,
    const float* __restrict__ wb, const float* __restrict__ bb) {
    extern __shared__ float psm[];  // [2][ A(128*36) + B(128*36) ]
    const int d = blockIdx.z;
    const float* __restrict__ w    = d ? wb : wf;
    const float* __restrict__ bias = d ? bb : bf;
    const int row0 = blockIdx.y * 128;
    const int col0 = blockIdx.x * 128;

    const int tid = threadIdx.x;
    const int lane = tid & 31, wid = tid >> 5;
    const int wm = wid >> 2, wn = wid & 3;
    const int g = lane >> 2, t4 = lane & 3;

    // per-thread tile-fragment coords for the loaders
    const int lm = tid >> 3, lk = (tid & 7) * 4;

    float acc[4][4][4];
#pragma unroll
    for (int i = 0; i < 4; i++)
#pragma unroll
        for (int j = 0; j < 4; j++)
#pragma unroll
            for (int r = 0; r < 4; r++) acc[i][j][r] = 0.f;

    float4 va[4], vb[4];
    auto ldg_tiles = [&](int k0) {
#pragma unroll
        for (int i = 0; i < 4; i++) {
            int m = lm + i * 32;
            int row = row0 + m;
            int t = row >> 4, b = row & 15;
            va[i] = *reinterpret_cast<const float4*>(
                x + (size_t)(b * TT + t) * EE + k0 + lk);
            vb[i] = *reinterpret_cast<const float4*>(
                w + (size_t)(col0 + m) * G3 + k0 + lk);
        }
    };
    auto sts_tiles = [&](float* As, float* Bs) {
#pragma unroll
        for (int i = 0; i < 4; i++) {
            int m = lm + i * 32;
            float4 oa = make_float4(f2tff(va[i].x), f2tff(va[i].y),
                                    f2tff(va[i].z), f2tff(va[i].w));
            float4 ob = make_float4(f2tff(vb[i].x), f2tff(vb[i].y),
                                    f2tff(vb[i].z), f2tff(vb[i].w));
            *reinterpret_cast<float4*>(&As[m * 36 + lk]) = oa;
            *reinterpret_cast<float4*>(&Bs[m * 36 + lk]) = ob;
        }
    };

    ldg_tiles(0);
    sts_tiles(psm, psm + PTILE);
    __syncthreads();

    for (int kb = 0; kb < 32; kb++) {
        const int p = kb & 1;
        float* As = psm + p * 2 * PTILE;
        float* Bs = As + PTILE;
        if (kb < 31) ldg_tiles((kb + 1) * 32);

#pragma unroll
        for (int kt = 0; kt < 4; kt++) {
            int k = kt * 8;
            uint32_t a[4][4];
#pragma unroll
            for (int mt = 0; mt < 4; mt++) {
                int mb = wm * 64 + mt * 16;
                a[mt][0] = __float_as_uint(As[(mb + g) * 36 + k + t4]);
                a[mt][1] = __float_as_uint(As[(mb + g + 8) * 36 + k + t4]);
                a[mt][2] = __float_as_uint(As[(mb + g) * 36 + k + 4 + t4]);
                a[mt][3] = __float_as_uint(As[(mb + g + 8) * 36 + k + 4 + t4]);
            }
#pragma unroll
            for (int nt = 0; nt < 4; nt++) {
                int nb = wn * 32 + nt * 8;
                uint32_t b0 = __float_as_uint(Bs[(nb + g) * 36 + k + t4]);
                uint32_t b1 = __float_as_uint(Bs[(nb + g) * 36 + k + 4 + t4]);
#pragma unroll
                for (int mt = 0; mt < 4; mt++)
                    mma8(acc[mt][nt][0], acc[mt][nt][1], acc[mt][nt][2], acc[mt][nt][3],
                         a[mt][0], a[mt][1], a[mt][2], a[mt][3], b0, b1);
            }
        }
        if (kb < 31) {
            float* Asn = psm + (1 - p) * 2 * PTILE;
            sts_tiles(Asn, Asn + PTILE);
        }
        __syncthreads();
    }

#pragma unroll
    for (int mt = 0; mt < 4; mt++) {
        int rowb = row0 + wm * 64 + mt * 16 + g;
#pragma unroll
        for (int nt = 0; nt < 4; nt++) {
            int colb = col0 + wn * 32 + nt * 8 + 2 * t4;
#pragma unroll
            for (int r = 0; r < 4; r++) {
                int row = rowb + ((r >= 2) ? 8 : 0);
                int col = colb + (r & 1);
                int t = row >> 4, b = row & 15;
                float v = acc[mt][nt][r] + __ldg(bias + col);
                g_preg[(((size_t)d * TT + t) * G3 + col) * BB + b] = v;
            }
        }
    }
}

// ---------------------------------------------------------------------------
// Phase 2: persistent recurrence. 128 CTAs (64/dir), 256 thr (8 warps).
// Data-as-flag handoff. Publish: epi threads transpose h through SMEM,
// bar.sync(1,128), then WARP 0 emits all 8 columns as st.relaxed.v4 ->
// each 128B line arrives from one warp instruction. Consumers run a merged
// poll-verify (8 v4 loads in flight per iteration). Fast MUFU gates.
// ---------------------------------------------------------------------------
#define WPAD 516
#define RPAD 25

__global__ __launch_bounds__(256) void recur_kernel(
    const float* __restrict__ wf, const float* __restrict__ wb,
    const float* __restrict__ h0f, const float* __restrict__ h0b,
    const float* __restrict__ c0f, const float* __restrict__ c0b,
    float* __restrict__ out) {
    extern __shared__ float sm[];
    float* hsm = sm;                       // 16 x WPAD
    float* red = sm + 16 * WPAD;           // 2 x 8 x 16 x RPAD (parity)
    float* hT  = red + 2 * 8 * 16 * RPAD;  // 8 x 20 transpose buffer

    const int d   = (int)blockIdx.x >> 6;
    const int grp = (int)blockIdx.x & 63;
    const int n0  = grp * 8;
    const float* __restrict__ w  = d ? wb : wf;
    const float* __restrict__ h0 = d ? h0b : h0f;
    const float* __restrict__ c0 = d ? c0b : c0f;
    const float* __restrict__ preg = g_preg + (size_t)d * TT * G3 * BB;
    float* __restrict__ hst = g_hstage + (size_t)d * TT * HH * BB;

    const int tid = threadIdx.x, lane = tid & 31, wid = tid >> 5;
    const int g = lane >> 2, t4 = lane & 3;
    const int eb = (tid >> 3) & 15, en = tid & 7;  // epilogue (batch, col)
    const bool epi = tid < 128;
    const int kbase = wid * 64;       // this warp's K slice
    const int k2 = tid * 2;           // the 2 k-columns I stage (one 128B line)

    // Preload this thread's W_h B-fragments into registers (tf32).
    float breg[8][3][2];
#pragma unroll
    for (int nt = 0; nt < 3; nt++) {
        const float* wr = w + (size_t)(nt * 512 + n0 + g) * G3 + 1024;
#pragma unroll
        for (int kt = 0; kt < 8; kt++) {
            int col = kbase + kt * 8;
            breg[kt][nt][0] = f2tff(__ldg(wr + col + t4));
            breg[kt][nt][1] = f2tff(__ldg(wr + col + 4 + t4));
        }
    }
    float c = epi ? c0[n0 + en] : 0.f;  // cell state in a register

    // step-0 h: broadcast h0 over batch into my 2 columns
    {
        float2 o = make_float2(f2tff(h0[k2]), f2tff(h0[k2 + 1]));
#pragma unroll
        for (int b = 0; b < 16; b++)
            *reinterpret_cast<float2*>(&hsm[b * WPAD + k2]) = o;
    }
    __syncthreads();

    for (int s = 0; s < TT; s++) {
        const int tt = d ? (TT - 1 - s) : s;
        const int par = s & 1;
        float* redp = red + par * (8 * 16 * RPAD);

        // pre-gate prefetch (independent; overlaps the poll below)
        float pgi = 0.f, pgj = 0.f, pgo = 0.f;
        if (epi) {
            pgi = __ldg(preg + ((size_t)tt * G3 + (n0 + en)) * BB + eb);
            pgj = __ldg(preg + ((size_t)tt * G3 + (512 + n0 + en)) * BB + eb);
            pgo = __ldg(preg + ((size_t)tt * G3 + (1024 + n0 + en)) * BB + eb);
        }

        if (s > 0) {
            // merged poll-verify on MY line: 8 v4 loads in flight / iteration
            const int tp = d ? (tt + 1) : (tt - 1);
            const float* sp = hst + ((size_t)tp * HH + k2) * BB;
            float4 v[8];
            for (;;) {
                bool bad = false;
#pragma unroll
                for (int q = 0; q < 8; q++) {
                    v[q] = ld_rlx4(sp + q * 4);
                    bad |= has_sent(v[q]);
                }
                if (!bad) break;
            }
            // transpose: v[0..3] = col k2 (b 0..15), v[4..7] = col k2+1
#pragma unroll
            for (int q = 0; q < 4; q++) {
                const float* a = &v[q].x;
                const float* bq = &v[4 + q].x;
#pragma unroll
                for (int r = 0; r < 4; r++)
                    *reinterpret_cast<float2*>(&hsm[(q * 4 + r) * WPAD + k2]) =
                        make_float2(a[r], bq[r]);
            }
        }
        __syncwarp();  // my warp's staging visible to my warp's mma

        // per-warp mma on its own K slice: A from SMEM, B from registers
        float acc[3][4];
#pragma unroll
        for (int nt = 0; nt < 3; nt++)
#pragma unroll
            for (int r = 0; r < 4; r++) acc[nt][r] = 0.f;

#pragma unroll
        for (int kt = 0; kt < 8; kt++) {
            int k = kbase + kt * 8;
            uint32_t a0 = __float_as_uint(hsm[g * WPAD + k + t4]);
            uint32_t a1 = __float_as_uint(hsm[(g + 8) * WPAD + k + t4]);
            uint32_t a2 = __float_as_uint(hsm[g * WPAD + k + 4 + t4]);
            uint32_t a3 = __float_as_uint(hsm[(g + 8) * WPAD + k + 4 + t4]);
#pragma unroll
            for (int nt = 0; nt < 3; nt++)
                mma8(acc[nt][0], acc[nt][1], acc[nt][2], acc[nt][3],
                     a0, a1, a2, a3,
                     __float_as_uint(breg[kt][nt][0]),
                     __float_as_uint(breg[kt][nt][1]));
        }

        // cross-warp K reduction via SMEM (parity-buffered)
        float* rw = redp + wid * 16 * RPAD;
#pragma unroll
        for (int nt = 0; nt < 3; nt++) {
            int rl = nt * 8 + 2 * t4;
            rw[g * RPAD + rl]           = acc[nt][0];
            rw[g * RPAD + rl + 1]       = acc[nt][1];
            rw[(g + 8) * RPAD + rl]     = acc[nt][2];
            rw[(g + 8) * RPAD + rl + 1] = acc[nt][3];
        }
        __syncthreads();  // the single CTA-wide barrier per step

        if (epi) {
            float si = pgi, sj = pgj, so = pgo;
#pragma unroll
            for (int wq = 0; wq < 8; wq++) {
                const float* rr = redp + (wq * 16 + eb) * RPAD;
                si += rr[en];
                sj += rr[8 + en];
                so += rr[16 + en];
            }
            // fast MUFU-only gates (err ~1e-6)
            float ig = rcpa(1.f + __expf(-si));
            float tj = 1.f - 2.f * rcpa(1.f + __expf(2.f * sj));
            c = (1.f - ig) * c + ig * tj;                       // coupled gate
            float tc = 1.f - 2.f * rcpa(1.f + __expf(2.f * c));
            float h = tc * rcpa(1.f + __expf(-so));

            // transpose h through SMEM, then warp 0 publishes whole columns
            hT[en * 20 + eb] = f2tff(h);
            out[(size_t)(eb * TT + tt) * 1024 + d * 512 + n0 + en] = h;
            asm volatile("bar.sync 1, 128;" ::: "memory");
            if (tid < 32) {
                int col = tid >> 2, q = tid & 3;
                float4 vv = *reinterpret_cast<float4*>(&hT[col * 20 + q * 4]);
                st_rlx4(hst + ((size_t)tt * HH + n0 + col) * BB + q * 4, vv);
            }
        }
    }
}

extern "C" void kernel_launch(void* const* d_in, const int* in_sizes, int n_in,
                              void* d_out, int out_size) {
    (void)in_sizes; (void)n_in; (void)out_size;
    const float* x   = (const float*)d_in[0];
    const float* wf  = (const float*)d_in[1];
    const float* bf  = (const float*)d_in[2];
    const float* wb  = (const float*)d_in[3];
    const float* bb  = (const float*)d_in[4];
    const float* h0f = (const float*)d_in[5];
    const float* h0b = (const float*)d_in[6];
    const float* c0f = (const float*)d_in[7];
    const float* c0b = (const float*)d_in[8];
    float* out = (float*)d_out;

    const int psm_bytes = 4 * PTILE * 4;  // 73728
    cudaFuncSetAttribute(pregemm_kernel, cudaFuncAttributeMaxDynamicSharedMemorySize,
                         psm_bytes);
    const int rsm_bytes = (16 * WPAD + 2 * 8 * 16 * RPAD + 8 * 20) * 4;  // 59264
    cudaFuncSetAttribute(recur_kernel, cudaFuncAttributeMaxDynamicSharedMemorySize,
                         rsm_bytes);

    fill_sentinel_kernel<<<512, 256>>>();
    dim3 g1(G3 / 128, (TT * BB) / 128, 2);
    pregemm_kernel<<<g1, 256, psm_bytes>>>(x, wf, bf, wb, bb);
    recur_kernel<<<128, 256, rsm_bytes>>>(wf, wb, h0f, h0b, c0f, c0b, out);
}

// round 8
// speedup vs baseline: 1.2958x; 1.2958x over previous
#include <cuda_runtime.h>
#include <cstdint>
#include <cstddef>

#define TT 512
#define BB 16
#define EE 1024
#define HH 512
#define G3 1536
#define SENT 0x7FC00001u

// pre-gate scratch [d][t][col][b]
__device__ float g_preg[(size_t)2 * TT * G3 * BB];
// tf32-pre-rounded h staging [d][t][k][b]; sentinel-filled each launch
__device__ float g_hstage[(size_t)2 * TT * HH * BB];

static __device__ __forceinline__ uint32_t f2tf(float f) {
    uint32_t r; asm("cvt.rna.tf32.f32 %0, %1;" : "=r"(r) : "f"(f)); return r;
}
static __device__ __forceinline__ float f2tff(float f) { return __uint_as_float(f2tf(f)); }
static __device__ __forceinline__ float rcpa(float x) {
    float r; asm("rcp.approx.f32 %0, %1;" : "=f"(r) : "f"(x)); return r;
}

static __device__ __forceinline__ void mma8(float& d0, float& d1, float& d2, float& d3,
                                            uint32_t a0, uint32_t a1, uint32_t a2, uint32_t a3,
                                            uint32_t b0, uint32_t b1) {
    asm volatile(
        "mma.sync.aligned.m16n8k8.row.col.f32.tf32.tf32.f32 "
        "{%0,%1,%2,%3}, {%4,%5,%6,%7}, {%8,%9}, {%0,%1,%2,%3};"
        : "+f"(d0), "+f"(d1), "+f"(d2), "+f"(d3)
        : "r"(a0), "r"(a1), "r"(a2), "r"(a3), "r"(b0), "r"(b1));
}

// L1-bypassing (gpu-scope) loads/stores for the producer-consumer handoff
static __device__ __forceinline__ float4 ld_rlx4(const float* p) {
    float4 v;
    asm volatile("ld.relaxed.gpu.global.v4.f32 {%0,%1,%2,%3}, [%4];"
                 : "=f"(v.x), "=f"(v.y), "=f"(v.z), "=f"(v.w) : "l"(p) : "memory");
    return v;
}
static __device__ __forceinline__ void st_rlx4(float* p, float4 v) {
    asm volatile("st.relaxed.gpu.global.v4.f32 [%0], {%1,%2,%3,%4};"
                 :: "l"(p), "f"(v.x), "f"(v.y), "f"(v.z), "f"(v.w) : "memory");
}
static __device__ __forceinline__ bool has_sent(float4 v) {
    return (__float_as_uint(v.x) == SENT) | (__float_as_uint(v.y) == SENT) |
           (__float_as_uint(v.z) == SENT) | (__float_as_uint(v.w) == SENT);
}

// fill g_hstage with the sentinel pattern (runs first, every launch)
__global__ void fill_sentinel_kernel() {
    const size_t n4 = (size_t)2 * TT * HH * BB / 4;
    uint4 s = make_uint4(SENT, SENT, SENT, SENT);
    uint4* p = reinterpret_cast<uint4*>(g_hstage);
    for (size_t i = blockIdx.x * (size_t)blockDim.x + threadIdx.x; i < n4;
         i += (size_t)gridDim.x * blockDim.x)
        p[i] = s;
}

// ---------------------------------------------------------------------------
// Phase 1: pre-gates = x @ W_x^T + bias, both directions (tf32 mma GEMM).
// M = 8192, N = 1536, K = 1024. CTA tile 128x128x32, 8 warps, warp 64x32.
// (simple static-SMEM version — the R7 double-buffer spilled and regressed)
// ---------------------------------------------------------------------------
__global__ __launch_bounds__(256) void pregemm_kernel(
    const float* __restrict__ x,
    const float* __restrict__ wf, const float* __restrict__ bf,
    const float* __restrict__ wb, const float* __restrict__ bb) {
    const int d = blockIdx.z;
    const float* __restrict__ w    = d ? wb : wf;
    const float* __restrict__ bias = d ? bb : bf;
    const int row0 = blockIdx.y * 128;
    const int col0 = blockIdx.x * 128;

    __shared__ float As[128][36];
    __shared__ float Bs[128][36];

    const int tid = threadIdx.x;
    const int lane = tid & 31, wid = tid >> 5;
    const int wm = wid >> 2, wn = wid & 3;
    const int g = lane >> 2, t4 = lane & 3;

    float acc[4][4][4];
#pragma unroll
    for (int i = 0; i < 4; i++)
#pragma unroll
        for (int j = 0; j < 4; j++)
#pragma unroll
            for (int r = 0; r < 4; r++) acc[i][j][r] = 0.f;

    for (int k0 = 0; k0 < EE; k0 += 32) {
#pragma unroll
        for (int i = 0; i < 4; i++) {
            int idx = tid + i * 256;
            int m = idx >> 3, kq = idx & 7;
            int row = row0 + m;
            int t = row >> 4, b = row & 15;
            float4 v = *reinterpret_cast<const float4*>(
                x + (size_t)(b * TT + t) * EE + k0 + kq * 4);
            float4 o = make_float4(f2tff(v.x), f2tff(v.y), f2tff(v.z), f2tff(v.w));
            *reinterpret_cast<float4*>(&As[m][kq * 4]) = o;
        }
#pragma unroll
        for (int i = 0; i < 4; i++) {
            int idx = tid + i * 256;
            int n = idx >> 3, kq = idx & 7;
            float4 v = *reinterpret_cast<const float4*>(
                w + (size_t)(col0 + n) * G3 + k0 + kq * 4);
            float4 o = make_float4(f2tff(v.x), f2tff(v.y), f2tff(v.z), f2tff(v.w));
            *reinterpret_cast<float4*>(&Bs[n][kq * 4]) = o;
        }
        __syncthreads();

#pragma unroll
        for (int kt = 0; kt < 4; kt++) {
            int k = kt * 8;
            uint32_t a[4][4];
#pragma unroll
            for (int mt = 0; mt < 4; mt++) {
                int mb = wm * 64 + mt * 16;
                a[mt][0] = __float_as_uint(As[mb + g][k + t4]);
                a[mt][1] = __float_as_uint(As[mb + g + 8][k + t4]);
                a[mt][2] = __float_as_uint(As[mb + g][k + 4 + t4]);
                a[mt][3] = __float_as_uint(As[mb + g + 8][k + 4 + t4]);
            }
#pragma unroll
            for (int nt = 0; nt < 4; nt++) {
                int nb = wn * 32 + nt * 8;
                uint32_t b0 = __float_as_uint(Bs[nb + g][k + t4]);
                uint32_t b1 = __float_as_uint(Bs[nb + g][k + 4 + t4]);
#pragma unroll
                for (int mt = 0; mt < 4; mt++)
                    mma8(acc[mt][nt][0], acc[mt][nt][1], acc[mt][nt][2], acc[mt][nt][3],
                         a[mt][0], a[mt][1], a[mt][2], a[mt][3], b0, b1);
            }
        }
        __syncthreads();
    }

#pragma unroll
    for (int mt = 0; mt < 4; mt++) {
        int rowb = row0 + wm * 64 + mt * 16 + g;
#pragma unroll
        for (int nt = 0; nt < 4; nt++) {
            int colb = col0 + wn * 32 + nt * 8 + 2 * t4;
#pragma unroll
            for (int r = 0; r < 4; r++) {
                int row = rowb + ((r >= 2) ? 8 : 0);
                int col = colb + (r & 1);
                int t = row >> 4, b = row & 15;
                float v = acc[mt][nt][r] + __ldg(bias + col);
                g_preg[(((size_t)d * TT + t) * G3 + col) * BB + b] = v;
            }
        }
    }
}

// ---------------------------------------------------------------------------
// Phase 2: persistent recurrence. 128 CTAs (64/dir), 256 thr (8 warps).
// Data-as-flag handoff. Publish: epi threads put full-precision h into an
// SMEM transpose buffer, bar.sync(1,128); warp 0 then emits hst columns
// (tf32-rounded in-flight) as st.relaxed.v4 AND out rows as coalesced v4
// pairs. Consumers: merged poll-verify (8 v4 loads in flight). MUFU gates.
// ---------------------------------------------------------------------------
#define WPAD 516
#define RPAD 25

__global__ __launch_bounds__(256) void recur_kernel(
    const float* __restrict__ wf, const float* __restrict__ wb,
    const float* __restrict__ h0f, const float* __restrict__ h0b,
    const float* __restrict__ c0f, const float* __restrict__ c0b,
    float* __restrict__ out) {
    extern __shared__ float sm[];
    float* hsm = sm;                       // 16 x WPAD
    float* red = sm + 16 * WPAD;           // 2 x 8 x 16 x RPAD (parity)
    float* hT  = red + 2 * 8 * 16 * RPAD;  // 8 x 20 transpose buffer (full prec)

    const int d   = (int)blockIdx.x >> 6;
    const int grp = (int)blockIdx.x & 63;
    const int n0  = grp * 8;
    const float* __restrict__ w  = d ? wb : wf;
    const float* __restrict__ h0 = d ? h0b : h0f;
    const float* __restrict__ c0 = d ? c0b : c0f;
    const float* __restrict__ preg = g_preg + (size_t)d * TT * G3 * BB;
    float* __restrict__ hst = g_hstage + (size_t)d * TT * HH * BB;

    const int tid = threadIdx.x, lane = tid & 31, wid = tid >> 5;
    const int g = lane >> 2, t4 = lane & 3;
    const int eb = (tid >> 3) & 15, en = tid & 7;  // epilogue (batch, col)
    const bool epi = tid < 128;
    const int kbase = wid * 64;       // this warp's K slice
    const int k2 = tid * 2;           // the 2 k-columns I stage (one 128B line)

    // Preload this thread's W_h B-fragments into registers (tf32).
    float breg[8][3][2];
#pragma unroll
    for (int nt = 0; nt < 3; nt++) {
        const float* wr = w + (size_t)(nt * 512 + n0 + g) * G3 + 1024;
#pragma unroll
        for (int kt = 0; kt < 8; kt++) {
            int col = kbase + kt * 8;
            breg[kt][nt][0] = f2tff(__ldg(wr + col + t4));
            breg[kt][nt][1] = f2tff(__ldg(wr + col + 4 + t4));
        }
    }
    float c = epi ? c0[n0 + en] : 0.f;  // cell state in a register

    // step-0 h: broadcast h0 over batch into my 2 columns
    {
        float2 o = make_float2(f2tff(h0[k2]), f2tff(h0[k2 + 1]));
#pragma unroll
        for (int b = 0; b < 16; b++)
            *reinterpret_cast<float2*>(&hsm[b * WPAD + k2]) = o;
    }
    __syncthreads();

    for (int s = 0; s < TT; s++) {
        const int tt = d ? (TT - 1 - s) : s;
        const int par = s & 1;
        float* redp = red + par * (8 * 16 * RPAD);

        // pre-gate prefetch (independent; overlaps the poll below)
        float pgi = 0.f, pgj = 0.f, pgo = 0.f;
        if (epi) {
            pgi = __ldg(preg + ((size_t)tt * G3 + (n0 + en)) * BB + eb);
            pgj = __ldg(preg + ((size_t)tt * G3 + (512 + n0 + en)) * BB + eb);
            pgo = __ldg(preg + ((size_t)tt * G3 + (1024 + n0 + en)) * BB + eb);
        }

        if (s > 0) {
            // merged poll-verify on MY line: 8 v4 loads in flight / iteration
            const int tp = d ? (tt + 1) : (tt - 1);
            const float* sp = hst + ((size_t)tp * HH + k2) * BB;
            float4 v[8];
            for (;;) {
                bool bad = false;
#pragma unroll
                for (int q = 0; q < 8; q++) {
                    v[q] = ld_rlx4(sp + q * 4);
                    bad |= has_sent(v[q]);
                }
                if (!bad) break;
            }
            // transpose: v[0..3] = col k2 (b 0..15), v[4..7] = col k2+1
#pragma unroll
            for (int q = 0; q < 4; q++) {
                const float* a = &v[q].x;
                const float* bq = &v[4 + q].x;
#pragma unroll
                for (int r = 0; r < 4; r++)
                    *reinterpret_cast<float2*>(&hsm[(q * 4 + r) * WPAD + k2]) =
                        make_float2(a[r], bq[r]);
            }
        }
        __syncwarp();  // my warp's staging visible to my warp's mma

        // per-warp mma on its own K slice: A from SMEM, B from registers
        float acc[3][4];
#pragma unroll
        for (int nt = 0; nt < 3; nt++)
#pragma unroll
            for (int r = 0; r < 4; r++) acc[nt][r] = 0.f;

#pragma unroll
        for (int kt = 0; kt < 8; kt++) {
            int k = kbase + kt * 8;
            uint32_t a0 = __float_as_uint(hsm[g * WPAD + k + t4]);
            uint32_t a1 = __float_as_uint(hsm[(g + 8) * WPAD + k + t4]);
            uint32_t a2 = __float_as_uint(hsm[g * WPAD + k + 4 + t4]);
            uint32_t a3 = __float_as_uint(hsm[(g + 8) * WPAD + k + 4 + t4]);
#pragma unroll
            for (int nt = 0; nt < 3; nt++)
                mma8(acc[nt][0], acc[nt][1], acc[nt][2], acc[nt][3],
                     a0, a1, a2, a3,
                     __float_as_uint(breg[kt][nt][0]),
                     __float_as_uint(breg[kt][nt][1]));
        }

        // cross-warp K reduction via SMEM (parity-buffered)
        float* rw = redp + wid * 16 * RPAD;
#pragma unroll
        for (int nt = 0; nt < 3; nt++) {
            int rl = nt * 8 + 2 * t4;
            rw[g * RPAD + rl]           = acc[nt][0];
            rw[g * RPAD + rl + 1]       = acc[nt][1];
            rw[(g + 8) * RPAD + rl]     = acc[nt][2];
            rw[(g + 8) * RPAD + rl + 1] = acc[nt][3];
        }
        __syncthreads();  // the single CTA-wide barrier per step

        if (epi) {
            float si = pgi, sj = pgj, so = pgo;
#pragma unroll
            for (int wq = 0; wq < 8; wq++) {
                const float* rr = redp + (wq * 16 + eb) * RPAD;
                si += rr[en];
                sj += rr[8 + en];
                so += rr[16 + en];
            }
            // fast MUFU-only gates (err ~1e-6)
            float ig = rcpa(1.f + __expf(-si));
            float tj = 1.f - 2.f * rcpa(1.f + __expf(2.f * sj));
            c = (1.f - ig) * c + ig * tj;                       // coupled gate
            float tc = 1.f - 2.f * rcpa(1.f + __expf(2.f * c));
            float h = tc * rcpa(1.f + __expf(-so));

            // full-precision h into the transpose buffer; warp 0 publishes
            hT[en * 20 + eb] = h;
            asm volatile("bar.sync 1, 128;" ::: "memory");
            if (tid < 32) {
                // hst publish: 8 columns x 16 batch, tf32-rounded in flight
                int col = tid >> 2, q = tid & 3;
                float4 vv = *reinterpret_cast<float4*>(&hT[col * 20 + q * 4]);
                vv = make_float4(f2tff(vv.x), f2tff(vv.y), f2tff(vv.z), f2tff(vv.w));
                st_rlx4(hst + ((size_t)tt * HH + n0 + col) * BB + q * 4, vv);
            }
            if (tid < 16) {
                // out rows: one batch per lane, two coalesced v4 stores
                float o0[8];
#pragma unroll
                for (int e = 0; e < 8; e++) o0[e] = hT[e * 20 + tid];
                float* op = out + (size_t)(tid * TT + tt) * 1024 + d * 512 + n0;
                *reinterpret_cast<float4*>(op) = make_float4(o0[0], o0[1], o0[2], o0[3]);
                *reinterpret_cast<float4*>(op + 4) = make_float4(o0[4], o0[5], o0[6], o0[7]);
            }
        }
    }
}

extern "C" void kernel_launch(void* const* d_in, const int* in_sizes, int n_in,
                              void* d_out, int out_size) {
    (void)in_sizes; (void)n_in; (void)out_size;
    const float* x   = (const float*)d_in[0];
    const float* wf  = (const float*)d_in[1];
    const float* bf  = (const float*)d_in[2];
    const float* wb  = (const float*)d_in[3];
    const float* bb  = (const float*)d_in[4];
    const float* h0f = (const float*)d_in[5];
    const float* h0b = (const float*)d_in[6];
    const float* c0f = (const float*)d_in[7];
    const float* c0b = (const float*)d_in[8];
    float* out = (float*)d_out;

    const int rsm_bytes = (16 * WPAD + 2 * 8 * 16 * RPAD + 8 * 20) * 4;  // 59264
    cudaFuncSetAttribute(recur_kernel, cudaFuncAttributeMaxDynamicSharedMemorySize,
                         rsm_bytes);

    fill_sentinel_kernel<<<512, 256>>>();
    dim3 g1(G3 / 128, (TT * BB) / 128, 2);
    pregemm_kernel<<<g1, 256>>>(x, wf, bf, wb, bb);
    recur_kernel<<<128, 256, rsm_bytes>>>(wf, wb, h0f, h0b, c0f, c0b, out);
}

// round 9
// speedup vs baseline: 1.6637x; 1.2839x over previous
#include <cuda_runtime.h>
#include <cstdint>
#include <cstddef>

#define TT 512
#define BB 16
#define EE 1024
#define HH 512
#define G3 1536
#define SENT 0x7FC00001u

// pre-gate scratch [d][t][col][b]
__device__ float g_preg[(size_t)2 * TT * G3 * BB];
// tf32-pre-rounded h staging [d][t][k][b]; sentinel-filled each launch
__device__ float g_hstage[(size_t)2 * TT * HH * BB];

static __device__ __forceinline__ uint32_t f2tf(float f) {
    uint32_t r; asm("cvt.rna.tf32.f32 %0, %1;" : "=r"(r) : "f"(f)); return r;
}
static __device__ __forceinline__ float f2tff(float f) { return __uint_as_float(f2tf(f)); }
static __device__ __forceinline__ float rcpa(float x) {
    float r; asm("rcp.approx.f32 %0, %1;" : "=f"(r) : "f"(x)); return r;
}

static __device__ __forceinline__ void mma8(float& d0, float& d1, float& d2, float& d3,
                                            uint32_t a0, uint32_t a1, uint32_t a2, uint32_t a3,
                                            uint32_t b0, uint32_t b1) {
    asm volatile(
        "mma.sync.aligned.m16n8k8.row.col.f32.tf32.tf32.f32 "
        "{%0,%1,%2,%3}, {%4,%5,%6,%7}, {%8,%9}, {%0,%1,%2,%3};"
        : "+f"(d0), "+f"(d1), "+f"(d2), "+f"(d3)
        : "r"(a0), "r"(a1), "r"(a2), "r"(a3), "r"(b0), "r"(b1));
}

// L1-bypassing (gpu-scope) loads/stores for the producer-consumer handoff
static __device__ __forceinline__ float4 ld_rlx4(const float* p) {
    float4 v;
    asm volatile("ld.relaxed.gpu.global.v4.f32 {%0,%1,%2,%3}, [%4];"
                 : "=f"(v.x), "=f"(v.y), "=f"(v.z), "=f"(v.w) : "l"(p) : "memory");
    return v;
}
static __device__ __forceinline__ void st_rlx(float* p, float v) {
    asm volatile("st.relaxed.gpu.global.f32 [%0], %1;" :: "l"(p), "f"(v) : "memory");
}
static __device__ __forceinline__ bool has_sent(float4 v) {
    return (__float_as_uint(v.x) == SENT) | (__float_as_uint(v.y) == SENT) |
           (__float_as_uint(v.z) == SENT) | (__float_as_uint(v.w) == SENT);
}

// fill g_hstage with the sentinel pattern (runs first, every launch)
__global__ void fill_sentinel_kernel() {
    const size_t n4 = (size_t)2 * TT * HH * BB / 4;
    uint4 s = make_uint4(SENT, SENT, SENT, SENT);
    uint4* p = reinterpret_cast<uint4*>(g_hstage);
    for (size_t i = blockIdx.x * (size_t)blockDim.x + threadIdx.x; i < n4;
         i += (size_t)gridDim.x * blockDim.x)
        p[i] = s;
}

// ---------------------------------------------------------------------------
// Phase 1: pre-gates = x @ W_x^T + bias, both directions (tf32 mma GEMM).
// M = 8192, N = 1536, K = 1024. CTA tile 128x128x32, 8 warps, warp 64x32.
// ---------------------------------------------------------------------------
__global__ __launch_bounds__(256) void pregemm_kernel(
    const float* __restrict__ x,
    const float* __restrict__ wf, const float* __restrict__ bf,
    const float* __restrict__ wb, const float* __restrict__ bb) {
    const int d = blockIdx.z;
    const float* __restrict__ w    = d ? wb : wf;
    const float* __restrict__ bias = d ? bb : bf;
    const int row0 = blockIdx.y * 128;
    const int col0 = blockIdx.x * 128;

    __shared__ float As[128][36];
    __shared__ float Bs[128][36];

    const int tid = threadIdx.x;
    const int lane = tid & 31, wid = tid >> 5;
    const int wm = wid >> 2, wn = wid & 3;
    const int g = lane >> 2, t4 = lane & 3;

    float acc[4][4][4];
#pragma unroll
    for (int i = 0; i < 4; i++)
#pragma unroll
        for (int j = 0; j < 4; j++)
#pragma unroll
            for (int r = 0; r < 4; r++) acc[i][j][r] = 0.f;

    for (int k0 = 0; k0 < EE; k0 += 32) {
#pragma unroll
        for (int i = 0; i < 4; i++) {
            int idx = tid + i * 256;
            int m = idx >> 3, kq = idx & 7;
            int row = row0 + m;
            int t = row >> 4, b = row & 15;
            float4 v = *reinterpret_cast<const float4*>(
                x + (size_t)(b * TT + t) * EE + k0 + kq * 4);
            float4 o = make_float4(f2tff(v.x), f2tff(v.y), f2tff(v.z), f2tff(v.w));
            *reinterpret_cast<float4*>(&As[m][kq * 4]) = o;
        }
#pragma unroll
        for (int i = 0; i < 4; i++) {
            int idx = tid + i * 256;
            int n = idx >> 3, kq = idx & 7;
            float4 v = *reinterpret_cast<const float4*>(
                w + (size_t)(col0 + n) * G3 + k0 + kq * 4);
            float4 o = make_float4(f2tff(v.x), f2tff(v.y), f2tff(v.z), f2tff(v.w));
            *reinterpret_cast<float4*>(&Bs[n][kq * 4]) = o;
        }
        __syncthreads();

#pragma unroll
        for (int kt = 0; kt < 4; kt++) {
            int k = kt * 8;
            uint32_t a[4][4];
#pragma unroll
            for (int mt = 0; mt < 4; mt++) {
                int mb = wm * 64 + mt * 16;
                a[mt][0] = __float_as_uint(As[mb + g][k + t4]);
                a[mt][1] = __float_as_uint(As[mb + g + 8][k + t4]);
                a[mt][2] = __float_as_uint(As[mb + g][k + 4 + t4]);
                a[mt][3] = __float_as_uint(As[mb + g + 8][k + 4 + t4]);
            }
#pragma unroll
            for (int nt = 0; nt < 4; nt++) {
                int nb = wn * 32 + nt * 8;
                uint32_t b0 = __float_as_uint(Bs[nb + g][k + t4]);
                uint32_t b1 = __float_as_uint(Bs[nb + g][k + 4 + t4]);
#pragma unroll
                for (int mt = 0; mt < 4; mt++)
                    mma8(acc[mt][nt][0], acc[mt][nt][1], acc[mt][nt][2], acc[mt][nt][3],
                         a[mt][0], a[mt][1], a[mt][2], a[mt][3], b0, b1);
            }
        }
        __syncthreads();
    }

#pragma unroll
    for (int mt = 0; mt < 4; mt++) {
        int rowb = row0 + wm * 64 + mt * 16 + g;
#pragma unroll
        for (int nt = 0; nt < 4; nt++) {
            int colb = col0 + wn * 32 + nt * 8 + 2 * t4;
#pragma unroll
            for (int r = 0; r < 4; r++) {
                int row = rowb + ((r >= 2) ? 8 : 0);
                int col = colb + (r & 1);
                int t = row >> 4, b = row & 15;
                float v = acc[mt][nt][r] + __ldg(bias + col);
                g_preg[(((size_t)d * TT + t) * G3 + col) * BB + b] = v;
            }
        }
    }
}

// ---------------------------------------------------------------------------
// Phase 2: persistent recurrence — EXACT R6 structure (best known config):
// data-as-flag, per-thread detect-then-verify poll, per-thread scalar
// st.relaxed publish. ONE change vs R6: MUFU-only gate math (no tanhf).
// ---------------------------------------------------------------------------
#define WPAD 516
#define RPAD 25

__global__ __launch_bounds__(256) void recur_kernel(
    const float* __restrict__ wf, const float* __restrict__ wb,
    const float* __restrict__ h0f, const float* __restrict__ h0b,
    const float* __restrict__ c0f, const float* __restrict__ c0b,
    float* __restrict__ out) {
    extern __shared__ float sm[];
    float* hsm = sm;                 // 16 x WPAD  (h_{t-1} [b][k])
    float* red = sm + 16 * WPAD;     // 2 x 8 x 16 x RPAD (parity-buffered)

    const int d   = (int)blockIdx.x >> 6;
    const int grp = (int)blockIdx.x & 63;
    const int n0  = grp * 8;
    const float* __restrict__ w  = d ? wb : wf;
    const float* __restrict__ h0 = d ? h0b : h0f;
    const float* __restrict__ c0 = d ? c0b : c0f;
    const float* __restrict__ preg = g_preg + (size_t)d * TT * G3 * BB;
    float* __restrict__ hst = g_hstage + (size_t)d * TT * HH * BB;

    const int tid = threadIdx.x, lane = tid & 31, wid = tid >> 5;
    const int g = lane >> 2, t4 = lane & 3;
    const int eb = (tid >> 3) & 15, en = tid & 7;  // epilogue (batch, col)
    const bool epi = tid < 128;
    const int kbase = wid * 64;       // this warp's K slice
    const int k2 = tid * 2;           // the 2 k-columns I stage (one 128B line)

    // Preload this thread's W_h B-fragments into registers (tf32).
    float breg[8][3][2];
#pragma unroll
    for (int nt = 0; nt < 3; nt++) {
        const float* wr = w + (size_t)(nt * 512 + n0 + g) * G3 + 1024;
#pragma unroll
        for (int kt = 0; kt < 8; kt++) {
            int col = kbase + kt * 8;
            breg[kt][nt][0] = f2tff(__ldg(wr + col + t4));
            breg[kt][nt][1] = f2tff(__ldg(wr + col + 4 + t4));
        }
    }
    float c = epi ? c0[n0 + en] : 0.f;  // cell state in a register

    // step-0 h: broadcast h0 over batch into my 2 columns
    {
        float2 o = make_float2(f2tff(h0[k2]), f2tff(h0[k2 + 1]));
#pragma unroll
        for (int b = 0; b < 16; b++)
            *reinterpret_cast<float2*>(&hsm[b * WPAD + k2]) = o;
    }
    __syncthreads();

    for (int s = 0; s < TT; s++) {
        const int tt = d ? (TT - 1 - s) : s;
        const int par = s & 1;
        float* redp = red + par * (8 * 16 * RPAD);

        // pre-gate prefetch (independent; overlaps the poll below)
        float pgi = 0.f, pgj = 0.f, pgo = 0.f;
        if (epi) {
            pgi = __ldg(preg + ((size_t)tt * G3 + (n0 + en)) * BB + eb);
            pgj = __ldg(preg + ((size_t)tt * G3 + (512 + n0 + en)) * BB + eb);
            pgo = __ldg(preg + ((size_t)tt * G3 + (1024 + n0 + en)) * BB + eb);
        }

        if (s > 0) {
            // poll MY line (data-as-flag): spin on first 16B, then verify all
            const int tp = d ? (tt + 1) : (tt - 1);
            const float* sp = hst + ((size_t)tp * HH + k2) * BB;
            float4 v[8];
            do { v[0] = ld_rlx4(sp); } while (has_sent(v[0]));
            for (;;) {
                bool bad = false;
#pragma unroll
                for (int q = 1; q < 8; q++) {
                    v[q] = ld_rlx4(sp + q * 4);
                    bad |= has_sent(v[q]);
                }
                if (!bad) break;
            }
            // transpose: v[0..3] = col k2 (b 0..15), v[4..7] = col k2+1
#pragma unroll
            for (int q = 0; q < 4; q++) {
                const float* a = &v[q].x;
                const float* bq = &v[4 + q].x;
#pragma unroll
                for (int r = 0; r < 4; r++)
                    *reinterpret_cast<float2*>(&hsm[(q * 4 + r) * WPAD + k2]) =
                        make_float2(a[r], bq[r]);
            }
        }
        __syncwarp();  // my warp's staging visible to my warp's mma

        // per-warp mma on its own K slice: A from SMEM, B from registers
        float acc[3][4];
#pragma unroll
        for (int nt = 0; nt < 3; nt++)
#pragma unroll
            for (int r = 0; r < 4; r++) acc[nt][r] = 0.f;

#pragma unroll
        for (int kt = 0; kt < 8; kt++) {
            int k = kbase + kt * 8;
            uint32_t a0 = __float_as_uint(hsm[g * WPAD + k + t4]);
            uint32_t a1 = __float_as_uint(hsm[(g + 8) * WPAD + k + t4]);
            uint32_t a2 = __float_as_uint(hsm[g * WPAD + k + 4 + t4]);
            uint32_t a3 = __float_as_uint(hsm[(g + 8) * WPAD + k + 4 + t4]);
#pragma unroll
            for (int nt = 0; nt < 3; nt++)
                mma8(acc[nt][0], acc[nt][1], acc[nt][2], acc[nt][3],
                     a0, a1, a2, a3,
                     __float_as_uint(breg[kt][nt][0]),
                     __float_as_uint(breg[kt][nt][1]));
        }

        // cross-warp K reduction via SMEM (parity-buffered)
        float* rw = redp + wid * 16 * RPAD;
#pragma unroll
        for (int nt = 0; nt < 3; nt++) {
            int rl = nt * 8 + 2 * t4;
            rw[g * RPAD + rl]           = acc[nt][0];
            rw[g * RPAD + rl + 1]       = acc[nt][1];
            rw[(g + 8) * RPAD + rl]     = acc[nt][2];
            rw[(g + 8) * RPAD + rl + 1] = acc[nt][3];
        }
        __syncthreads();  // the single CTA-wide barrier per step

        if (epi) {
            float si = pgi, sj = pgj, so = pgo;
#pragma unroll
            for (int wq = 0; wq < 8; wq++) {
                const float* rr = redp + (wq * 16 + eb) * RPAD;
                si += rr[en];
                sj += rr[8 + en];
                so += rr[16 + en];
            }
            // fast MUFU-only gates (err ~1e-6) — the single change vs R6
            float ig = rcpa(1.f + __expf(-si));
            float tj = 1.f - 2.f * rcpa(1.f + __expf(2.f * sj));
            c = (1.f - ig) * c + ig * tj;                       // coupled gate
            float tc = 1.f - 2.f * rcpa(1.f + __expf(2.f * c));
            float h = tc * rcpa(1.f + __expf(-so));

            // publish: tf32-rounded h to the staging buffer (L2-direct),
            // full-precision h to the final output (exact R6 path)
            st_rlx(hst + ((size_t)tt * HH + n0 + en) * BB + eb, f2tff(h));
            out[(size_t)(eb * TT + tt) * 1024 + d * 512 + n0 + en] = h;
        }
    }
}

extern "C" void kernel_launch(void* const* d_in, const int* in_sizes, int n_in,
                              void* d_out, int out_size) {
    (void)in_sizes; (void)n_in; (void)out_size;
    const float* x   = (const float*)d_in[0];
    const float* wf  = (const float*)d_in[1];
    const float* bf  = (const float*)d_in[2];
    const float* wb  = (const float*)d_in[3];
    const float* bb  = (const float*)d_in[4];
    const float* h0f = (const float*)d_in[5];
    const float* h0b = (const float*)d_in[6];
    const float* c0f = (const float*)d_in[7];
    const float* c0b = (const float*)d_in[8];
    float* out = (float*)d_out;

    const int rsm_bytes = (16 * WPAD + 2 * 8 * 16 * RPAD) * 4;  // 58624
    cudaFuncSetAttribute(recur_kernel, cudaFuncAttributeMaxDynamicSharedMemorySize,
                         rsm_bytes);

    fill_sentinel_kernel<<<512, 256>>>();
    dim3 g1(G3 / 128, (TT * BB) / 128, 2);
    pregemm_kernel<<<g1, 256>>>(x, wf, bf, wb, bb);
    recur_kernel<<<128, 256, rsm_bytes>>>(wf, wb, h0f, h0b, c0f, c0b, out);
}

// round 10
// speedup vs baseline: 1.6964x; 1.0197x over previous
#include <cuda_runtime.h>
#include <cstdint>
#include <cstddef>

#define TT 512
#define BB 16
#define EE 1024
#define HH 512
#define G3 1536
#define SENT 0x7FC00001u

// pre-gate scratch [d][t][col][b]
__device__ float g_preg[(size_t)2 * TT * G3 * BB];
// tf32-pre-rounded h staging [d][t][k][b]; sentinel-filled each launch
__device__ float g_hstage[(size_t)2 * TT * HH * BB];

static __device__ __forceinline__ uint32_t f2tf(float f) {
    uint32_t r; asm("cvt.rna.tf32.f32 %0, %1;" : "=r"(r) : "f"(f)); return r;
}
static __device__ __forceinline__ float f2tff(float f) { return __uint_as_float(f2tf(f)); }
static __device__ __forceinline__ float rcpa(float x) {
    float r; asm("rcp.approx.f32 %0, %1;" : "=f"(r) : "f"(x)); return r;
}

static __device__ __forceinline__ void mma8(float& d0, float& d1, float& d2, float& d3,
                                            uint32_t a0, uint32_t a1, uint32_t a2, uint32_t a3,
                                            uint32_t b0, uint32_t b1) {
    asm volatile(
        "mma.sync.aligned.m16n8k8.row.col.f32.tf32.tf32.f32 "
        "{%0,%1,%2,%3}, {%4,%5,%6,%7}, {%8,%9}, {%0,%1,%2,%3};"
        : "+f"(d0), "+f"(d1), "+f"(d2), "+f"(d3)
        : "r"(a0), "r"(a1), "r"(a2), "r"(a3), "r"(b0), "r"(b1));
}

// L1-bypassing (gpu-scope) loads/stores for the producer-consumer handoff
static __device__ __forceinline__ float4 ld_rlx4(const float* p) {
    float4 v;
    asm volatile("ld.relaxed.gpu.global.v4.f32 {%0,%1,%2,%3}, [%4];"
                 : "=f"(v.x), "=f"(v.y), "=f"(v.z), "=f"(v.w) : "l"(p) : "memory");
    return v;
}
static __device__ __forceinline__ void st_rlx(float* p, float v) {
    asm volatile("st.relaxed.gpu.global.f32 [%0], %1;" :: "l"(p), "f"(v) : "memory");
}
static __device__ __forceinline__ bool has_sent(float4 v) {
    return (__float_as_uint(v.x) == SENT) | (__float_as_uint(v.y) == SENT) |
           (__float_as_uint(v.z) == SENT) | (__float_as_uint(v.w) == SENT);
}

// fill g_hstage with the sentinel pattern (runs first, every launch)
__global__ void fill_sentinel_kernel() {
    const size_t n4 = (size_t)2 * TT * HH * BB / 4;
    uint4 s = make_uint4(SENT, SENT, SENT, SENT);
    uint4* p = reinterpret_cast<uint4*>(g_hstage);
    for (size_t i = blockIdx.x * (size_t)blockDim.x + threadIdx.x; i < n4;
         i += (size_t)gridDim.x * blockDim.x)
        p[i] = s;
}

// ---------------------------------------------------------------------------
// Phase 1: pre-gates = x @ W_x^T + bias, both directions (tf32 mma GEMM).
// M = 8192, N = 1536, K = 1024. CTA tile 128x128x32, 8 warps, warp 64x32.
// ---------------------------------------------------------------------------
__global__ __launch_bounds__(256) void pregemm_kernel(
    const float* __restrict__ x,
    const float* __restrict__ wf, const float* __restrict__ bf,
    const float* __restrict__ wb, const float* __restrict__ bb) {
    const int d = blockIdx.z;
    const float* __restrict__ w    = d ? wb : wf;
    const float* __restrict__ bias = d ? bb : bf;
    const int row0 = blockIdx.y * 128;
    const int col0 = blockIdx.x * 128;

    __shared__ float As[128][36];
    __shared__ float Bs[128][36];

    const int tid = threadIdx.x;
    const int lane = tid & 31, wid = tid >> 5;
    const int wm = wid >> 2, wn = wid & 3;
    const int g = lane >> 2, t4 = lane & 3;

    float acc[4][4][4];
#pragma unroll
    for (int i = 0; i < 4; i++)
#pragma unroll
        for (int j = 0; j < 4; j++)
#pragma unroll
            for (int r = 0; r < 4; r++) acc[i][j][r] = 0.f;

    for (int k0 = 0; k0 < EE; k0 += 32) {
#pragma unroll
        for (int i = 0; i < 4; i++) {
            int idx = tid + i * 256;
            int m = idx >> 3, kq = idx & 7;
            int row = row0 + m;
            int t = row >> 4, b = row & 15;
            float4 v = *reinterpret_cast<const float4*>(
                x + (size_t)(b * TT + t) * EE + k0 + kq * 4);
            float4 o = make_float4(f2tff(v.x), f2tff(v.y), f2tff(v.z), f2tff(v.w));
            *reinterpret_cast<float4*>(&As[m][kq * 4]) = o;
        }
#pragma unroll
        for (int i = 0; i < 4; i++) {
            int idx = tid + i * 256;
            int n = idx >> 3, kq = idx & 7;
            float4 v = *reinterpret_cast<const float4*>(
                w + (size_t)(col0 + n) * G3 + k0 + kq * 4);
            float4 o = make_float4(f2tff(v.x), f2tff(v.y), f2tff(v.z), f2tff(v.w));
            *reinterpret_cast<float4*>(&Bs[n][kq * 4]) = o;
        }
        __syncthreads();

#pragma unroll
        for (int kt = 0; kt < 4; kt++) {
            int k = kt * 8;
            uint32_t a[4][4];
#pragma unroll
            for (int mt = 0; mt < 4; mt++) {
                int mb = wm * 64 + mt * 16;
                a[mt][0] = __float_as_uint(As[mb + g][k + t4]);
                a[mt][1] = __float_as_uint(As[mb + g + 8][k + t4]);
                a[mt][2] = __float_as_uint(As[mb + g][k + 4 + t4]);
                a[mt][3] = __float_as_uint(As[mb + g + 8][k + 4 + t4]);
            }
#pragma unroll
            for (int nt = 0; nt < 4; nt++) {
                int nb = wn * 32 + nt * 8;
                uint32_t b0 = __float_as_uint(Bs[nb + g][k + t4]);
                uint32_t b1 = __float_as_uint(Bs[nb + g][k + 4 + t4]);
#pragma unroll
                for (int mt = 0; mt < 4; mt++)
                    mma8(acc[mt][nt][0], acc[mt][nt][1], acc[mt][nt][2], acc[mt][nt][3],
                         a[mt][0], a[mt][1], a[mt][2], a[mt][3], b0, b1);
            }
        }
        __syncthreads();
    }

#pragma unroll
    for (int mt = 0; mt < 4; mt++) {
        int rowb = row0 + wm * 64 + mt * 16 + g;
#pragma unroll
        for (int nt = 0; nt < 4; nt++) {
            int colb = col0 + wn * 32 + nt * 8 + 2 * t4;
#pragma unroll
            for (int r = 0; r < 4; r++) {
                int row = rowb + ((r >= 2) ? 8 : 0);
                int col = colb + (r & 1);
                int t = row >> 4, b = row & 15;
                float v = acc[mt][nt][r] + __ldg(bias + col);
                g_preg[(((size_t)d * TT + t) * G3 + col) * BB + b] = v;
            }
        }
    }
}

// ---------------------------------------------------------------------------
// Phase 2: persistent recurrence — R6 structure with ONE mechanism change:
// epilogue remapped to (eb = tid&15, en = tid>>4) so each epi WARP owns one
// complete 128B hst line; its publish is a single coalesced 128B wavefront
// (atomic-ish arrival -> verify passes first try). The scattered `out`
// store moves off the critical path: h goes to a parity SMEM buffer and the
// previous step's out is written (coalesced, old mapping) after the reduce
// barrier of the next step.
// ---------------------------------------------------------------------------
#define WPAD 516
#define RPAD 25

__global__ __launch_bounds__(256) void recur_kernel(
    const float* __restrict__ wf, const float* __restrict__ wb,
    const float* __restrict__ h0f, const float* __restrict__ h0b,
    const float* __restrict__ c0f, const float* __restrict__ c0b,
    float* __restrict__ out) {
    extern __shared__ float sm[];
    float* hsm = sm;                       // 16 x WPAD  (h_{t-1} [b][k])
    float* red = sm + 16 * WPAD;           // 2 x 8 x 16 x RPAD (parity)
    float* hT  = red + 2 * 8 * 16 * RPAD;  // 2 x 8 x 20 parity h buffer

    const int d   = (int)blockIdx.x >> 6;
    const int grp = (int)blockIdx.x & 63;
    const int n0  = grp * 8;
    const float* __restrict__ w  = d ? wb : wf;
    const float* __restrict__ h0 = d ? h0b : h0f;
    const float* __restrict__ c0 = d ? c0b : c0f;
    const float* __restrict__ preg = g_preg + (size_t)d * TT * G3 * BB;
    float* __restrict__ hst = g_hstage + (size_t)d * TT * HH * BB;

    const int tid = threadIdx.x, lane = tid & 31, wid = tid >> 5;
    const int g = lane >> 2, t4 = lane & 3;
    // NEW epilogue mapping: warp w owns cols 2w,2w+1 x all 16 batches
    const int eb = tid & 15, en = (tid >> 4) & 7;
    // out-writeback mapping (coalesced): consecutive lanes -> consecutive cols
    const int en2 = tid & 7, eb2 = (tid >> 3) & 15;
    const bool epi = tid < 128;
    const int kbase = wid * 64;       // this warp's K slice
    const int k2 = tid * 2;           // the 2 k-columns I stage (one 128B line)

    // Preload this thread's W_h B-fragments into registers (tf32).
    float breg[8][3][2];
#pragma unroll
    for (int nt = 0; nt < 3; nt++) {
        const float* wr = w + (size_t)(nt * 512 + n0 + g) * G3 + 1024;
#pragma unroll
        for (int kt = 0; kt < 8; kt++) {
            int col = kbase + kt * 8;
            breg[kt][nt][0] = f2tff(__ldg(wr + col + t4));
            breg[kt][nt][1] = f2tff(__ldg(wr + col + 4 + t4));
        }
    }
    float c = epi ? c0[n0 + en] : 0.f;  // cell state in a register

    // step-0 h: broadcast h0 over batch into my 2 columns
    {
        float2 o = make_float2(f2tff(h0[k2]), f2tff(h0[k2 + 1]));
#pragma unroll
        for (int b = 0; b < 16; b++)
            *reinterpret_cast<float2*>(&hsm[b * WPAD + k2]) = o;
    }
    __syncthreads();

    for (int s = 0; s < TT; s++) {
        const int tt = d ? (TT - 1 - s) : s;
        const int par = s & 1;
        float* redp = red + par * (8 * 16 * RPAD);

        // pre-gate prefetch (independent; overlaps the poll below)
        float pgi = 0.f, pgj = 0.f, pgo = 0.f;
        if (epi) {
            pgi = __ldg(preg + ((size_t)tt * G3 + (n0 + en)) * BB + eb);
            pgj = __ldg(preg + ((size_t)tt * G3 + (512 + n0 + en)) * BB + eb);
            pgo = __ldg(preg + ((size_t)tt * G3 + (1024 + n0 + en)) * BB + eb);
        }

        if (s > 0) {
            // poll MY line (data-as-flag): spin on first 16B, then verify all
            const int tp = d ? (tt + 1) : (tt - 1);
            const float* sp = hst + ((size_t)tp * HH + k2) * BB;
            float4 v[8];
            do { v[0] = ld_rlx4(sp); } while (has_sent(v[0]));
            for (;;) {
                bool bad = false;
#pragma unroll
                for (int q = 1; q < 8; q++) {
                    v[q] = ld_rlx4(sp + q * 4);
                    bad |= has_sent(v[q]);
                }
                if (!bad) break;
            }
            // transpose: v[0..3] = col k2 (b 0..15), v[4..7] = col k2+1
#pragma unroll
            for (int q = 0; q < 4; q++) {
                const float* a = &v[q].x;
                const float* bq = &v[4 + q].x;
#pragma unroll
                for (int r = 0; r < 4; r++)
                    *reinterpret_cast<float2*>(&hsm[(q * 4 + r) * WPAD + k2]) =
                        make_float2(a[r], bq[r]);
            }
        }
        __syncwarp();  // my warp's staging visible to my warp's mma

        // per-warp mma on its own K slice: A from SMEM, B from registers
        float acc[3][4];
#pragma unroll
        for (int nt = 0; nt < 3; nt++)
#pragma unroll
            for (int r = 0; r < 4; r++) acc[nt][r] = 0.f;

#pragma unroll
        for (int kt = 0; kt < 8; kt++) {
            int k = kbase + kt * 8;
            uint32_t a0 = __float_as_uint(hsm[g * WPAD + k + t4]);
            uint32_t a1 = __float_as_uint(hsm[(g + 8) * WPAD + k + t4]);
            uint32_t a2 = __float_as_uint(hsm[g * WPAD + k + 4 + t4]);
            uint32_t a3 = __float_as_uint(hsm[(g + 8) * WPAD + k + 4 + t4]);
#pragma unroll
            for (int nt = 0; nt < 3; nt++)
                mma8(acc[nt][0], acc[nt][1], acc[nt][2], acc[nt][3],
                     a0, a1, a2, a3,
                     __float_as_uint(breg[kt][nt][0]),
                     __float_as_uint(breg[kt][nt][1]));
        }

        // cross-warp K reduction via SMEM (parity-buffered)
        float* rw = redp + wid * 16 * RPAD;
#pragma unroll
        for (int nt = 0; nt < 3; nt++) {
            int rl = nt * 8 + 2 * t4;
            rw[g * RPAD + rl]           = acc[nt][0];
            rw[g * RPAD + rl + 1]       = acc[nt][1];
            rw[(g + 8) * RPAD + rl]     = acc[nt][2];
            rw[(g + 8) * RPAD + rl + 1] = acc[nt][3];
        }
        __syncthreads();  // the single CTA-wide barrier per step

        if (epi) {
            float si = pgi, sj = pgj, so = pgo;
#pragma unroll
            for (int wq = 0; wq < 8; wq++) {
                const float* rr = redp + (wq * 16 + eb) * RPAD;
                si += rr[en];
                sj += rr[8 + en];
                so += rr[16 + en];
            }
            // fast MUFU-only gates (err ~1e-6)
            float ig = rcpa(1.f + __expf(-si));
            float tj = 1.f - 2.f * rcpa(1.f + __expf(2.f * sj));
            c = (1.f - ig) * c + ig * tj;                       // coupled gate
            float tc = 1.f - 2.f * rcpa(1.f + __expf(2.f * c));
            float h = tc * rcpa(1.f + __expf(-so));

            // publish FIRST: my warp owns one full 128B hst line -> one
            // coalesced wavefront, atomic-ish arrival at L2
            st_rlx(hst + ((size_t)tt * HH + n0 + en) * BB + eb, f2tff(h));
            // stash full-precision h for the deferred out write
            hT[par * 160 + en * 20 + eb] = h;

            // deferred coalesced out write for step s-1 (off critical path)
            if (s > 0) {
                const float* hTp = hT + (par ^ 1) * 160;
                const int tprev = d ? (TT - s) : (s - 1);
                out[(size_t)(eb2 * TT + tprev) * 1024 + d * 512 + n0 + en2] =
                    hTp[en2 * 20 + eb2];
            }
        }
    }

    // flush the final step's out values
    __syncthreads();
    if (epi) {
        const float* hTp = hT + ((TT - 1) & 1) * 160;
        const int tlast = d ? 0 : (TT - 1);
        out[(size_t)(eb2 * TT + tlast) * 1024 + d * 512 + n0 + en2] =
            hTp[en2 * 20 + eb2];
    }
}

extern "C" void kernel_launch(void* const* d_in, const int* in_sizes, int n_in,
                              void* d_out, int out_size) {
    (void)in_sizes; (void)n_in; (void)out_size;
    const float* x   = (const float*)d_in[0];
    const float* wf  = (const float*)d_in[1];
    const float* bf  = (const float*)d_in[2];
    const float* wb  = (const float*)d_in[3];
    const float* bb  = (const float*)d_in[4];
    const float* h0f = (const float*)d_in[5];
    const float* h0b = (const float*)d_in[6];
    const float* c0f = (const float*)d_in[7];
    const float* c0b = (const float*)d_in[8];
    float* out = (float*)d_out;

    const int rsm_bytes = (16 * WPAD + 2 * 8 * 16 * RPAD + 2 * 160) * 4;  // 59904
    cudaFuncSetAttribute(recur_kernel, cudaFuncAttributeMaxDynamicSharedMemorySize,
                         rsm_bytes);

    fill_sentinel_kernel<<<512, 256>>>();
    dim3 g1(G3 / 128, (TT * BB) / 128, 2);
    pregemm_kernel<<<g1, 256>>>(x, wf, bf, wb, bb);
    recur_kernel<<<128, 256, rsm_bytes>>>(wf, wb, h0f, h0b, c0f, c0b, out);
}